// round 5
// baseline (speedup 1.0000x reference)
#include <cuda_runtime.h>
#include <cuda_fp16.h>
#include <cstdint>

#define NUM_CODES 512
#define DIMS      64
#define HT        4096
#define N_VEC     131072
#define ZQ_SIZE   8388608
#define CTA_M     256
#define THREADS   256
#define GAP_TAU   0.02f

// ---- dynamic smem layout (bytes), MMA regions 1024-aligned for SW128 ----
#define SM_AHI   0
#define SM_ALO   32768
#define SM_BHI   65536
#define SM_BLO   131072
#define SM_ESQ   196608
#define SM_BI    198656
#define SM_BI2   199680
#define SM_GAP   200704
#define SM_WSUM  201728
#define SMEM_TOTAL 201792

__device__ float g_part[512];
__device__ int   g_counts[NUM_CODES];

#define SW(x) ((x) ^ ((((uint32_t)(x)) >> 3) & 0x70))

__device__ __forceinline__ uint32_t smem_u32(const void* p) {
    uint32_t a;
    asm("{ .reg .u64 t; cvta.to.shared.u64 t, %1; cvt.u32.u64 %0, t; }" : "=r"(a) : "l"(p));
    return a;
}
__device__ __forceinline__ void ldsm_x4(uint32_t& r0, uint32_t& r1, uint32_t& r2, uint32_t& r3, uint32_t a) {
    asm volatile("ldmatrix.sync.aligned.m8n8.x4.shared.b16 {%0,%1,%2,%3}, [%4];"
                 : "=r"(r0), "=r"(r1), "=r"(r2), "=r"(r3) : "r"(a));
}
__device__ __forceinline__ void mma16816(float* c, const uint32_t* a, uint32_t b0, uint32_t b1) {
    asm volatile("mma.sync.aligned.m16n8k16.row.col.f32.f16.f16.f32 "
                 "{%0,%1,%2,%3}, {%4,%5,%6,%7}, {%8,%9}, {%0,%1,%2,%3};"
                 : "+f"(c[0]), "+f"(c[1]), "+f"(c[2]), "+f"(c[3])
                 : "r"(a[0]), "r"(a[1]), "r"(a[2]), "r"(a[3]), "r"(b0), "r"(b1));
}
__device__ __forceinline__ uint32_t h2u(__half2 h) { return reinterpret_cast<uint32_t&>(h); }
__device__ __forceinline__ float2   u2f(uint32_t u) { __half2 h = reinterpret_cast<__half2&>(u); return __half22float2(h); }

__global__ void vq_init() {
    if (threadIdx.x < NUM_CODES) g_counts[threadIdx.x] = 0;
}

__global__ __launch_bounds__(THREADS, 1) void vq_main(
    const float* __restrict__ z_e, const float* __restrict__ embed,
    float* __restrict__ out)
{
    extern __shared__ char smem[];
    const uint32_t sbase = smem_u32(smem);
    const int tid = threadIdx.x, wid = tid >> 5, lid = tid & 31;

    // ---------- A fill: this thread's z vector -> f16 hi/lo, SW128 ----------
    const int n = blockIdx.x * CTA_M + tid;
    const int b = n >> 12, r = n & 4095;
    const float* zp = z_e + (size_t)b * (DIMS * HT) + r;

    #pragma unroll
    for (int i = 0; i < 8; i++) {
        uint32_t zh[4], zl[4];
        #pragma unroll
        for (int j = 0; j < 4; j++) {
            float x0 = zp[(8 * i + 2 * j) * HT];
            float x1 = zp[(8 * i + 2 * j + 1) * HT];
            __half h0 = __float2half_rn(x0), h1 = __float2half_rn(x1);
            __half l0 = __float2half_rn(x0 - __half2float(h0));
            __half l1 = __float2half_rn(x1 - __half2float(h1));
            zh[j] = h2u(__halves2half2(h0, h1));
            zl[j] = h2u(__halves2half2(l0, l1));
        }
        uint32_t off = SW(tid * 128 + i * 16);
        *(uint4*)(smem + SM_AHI + off) = make_uint4(zh[0], zh[1], zh[2], zh[3]);
        *(uint4*)(smem + SM_ALO + off) = make_uint4(zl[0], zl[1], zl[2], zl[3]);
    }

    // ---------- B fill: embedding (512x64 fp32) -> f16 hi/lo, SW128 ----------
    {
        const float4* e4 = (const float4*)embed;
        #pragma unroll 8
        for (int i = tid; i < NUM_CODES * DIMS / 4; i += THREADS) {
            float4 f = e4[i];
            int row = i >> 4, dg = i & 15;
            __half hx = __float2half_rn(f.x), hy = __float2half_rn(f.y);
            __half hz = __float2half_rn(f.z), hw = __float2half_rn(f.w);
            __half lx = __float2half_rn(f.x - __half2float(hx));
            __half ly = __float2half_rn(f.y - __half2float(hy));
            __half lz = __float2half_rn(f.z - __half2float(hz));
            __half lw = __float2half_rn(f.w - __half2float(hw));
            uint32_t off = SW(row * 128 + dg * 8);
            *(uint2*)(smem + SM_BHI + off) = make_uint2(h2u(__halves2half2(hx, hy)), h2u(__halves2half2(hz, hw)));
            *(uint2*)(smem + SM_BLO + off) = make_uint2(h2u(__halves2half2(lx, ly)), h2u(__halves2half2(lz, lw)));
        }
    }
    __syncthreads();

    // ---------- e_sq per code ----------
    float* esq = (float*)(smem + SM_ESQ);
    for (int rr = tid; rr < NUM_CODES; rr += THREADS) {
        float s = 0.f;
        #pragma unroll
        for (int dg = 0; dg < 16; dg++) {
            uint32_t off = SW(rr * 128 + dg * 8);
            uint2 hv = *(uint2*)(smem + SM_BHI + off);
            uint2 lv = *(uint2*)(smem + SM_BLO + off);
            float2 a = u2f(hv.x), al = u2f(lv.x), c = u2f(hv.y), cl = u2f(lv.y);
            float v0 = a.x + al.x, v1 = a.y + al.y, v2 = c.x + cl.x, v3 = c.y + cl.y;
            s += v0 * v0 + v1 * v1 + v2 * v2 + v3 * v3;
        }
        esq[rr] = s;
    }
    __syncthreads();

    // ---------- A hi fragments resident (warp rows rbase..rbase+31) ----------
    const int rbase = wid * 32;
    uint32_t a_hi[2][4][4];
    {
        const int g = lid >> 3;
        #pragma unroll
        for (int mt = 0; mt < 2; mt++)
            #pragma unroll
            for (int kt = 0; kt < 4; kt++) {
                uint32_t row = rbase + mt * 16 + ((g & 1) << 3) + (lid & 7);
                uint32_t byte = row * 128 + kt * 32 + ((g >> 1) << 4);
                ldsm_x4(a_hi[mt][kt][0], a_hi[mt][kt][1], a_hi[mt][kt][2], a_hi[mt][kt][3],
                        sbase + SM_AHI + SW(byte));
            }
    }

    // ---------- main loop: 32 n-tile pairs, hi*hi only ----------
    float b1[4] = {3.4e38f, 3.4e38f, 3.4e38f, 3.4e38f};
    float b2[4] = {3.4e38f, 3.4e38f, 3.4e38f, 3.4e38f};
    int   i1[4] = {0, 0, 0, 0}, i2[4] = {0, 0, 0, 0};
    // ldsm_x4 B address: 16 rows x 32 bytes per kt
    const uint32_t brow = ((lid >> 4) << 3) + (lid & 7);
    const uint32_t bk_off = ((lid >> 3) & 1) << 4;

    #pragma unroll 2
    for (int ntp = 0; ntp < 32; ntp++) {
        float acc[2][2][4] = {{{0.f,0.f,0.f,0.f},{0.f,0.f,0.f,0.f}},
                              {{0.f,0.f,0.f,0.f},{0.f,0.f,0.f,0.f}}};
        #pragma unroll
        for (int kt = 0; kt < 4; kt++) {
            uint32_t byte = (ntp * 16 + brow) * 128 + kt * 32 + bk_off;
            uint32_t bb0, bb1, bb2, bb3;
            ldsm_x4(bb0, bb1, bb2, bb3, sbase + SM_BHI + SW(byte));
            #pragma unroll
            for (int mt = 0; mt < 2; mt++) {
                mma16816(acc[0][mt], a_hi[mt][kt], bb0, bb1);
                mma16816(acc[1][mt], a_hi[mt][kt], bb2, bb3);
            }
        }
        #pragma unroll
        for (int h = 0; h < 2; h++)
            #pragma unroll
            for (int mt = 0; mt < 2; mt++)
                #pragma unroll
                for (int i = 0; i < 4; i++) {
                    int s = mt * 2 + (i >> 1);
                    int k = ntp * 16 + h * 8 + 2 * (lid & 3) + (i & 1);
                    float dist = esq[k] - 2.f * acc[h][mt][i];
                    if (dist < b1[s])      { b2[s] = b1[s]; i2[s] = i1[s]; b1[s] = dist; i1[s] = k; }
                    else if (dist < b2[s]) { b2[s] = dist; i2[s] = k; }
                }
    }

    // ---------- reduce (best,best2) across the 4 quad lanes ----------
    #pragma unroll
    for (int off = 1; off <= 2; off <<= 1) {
        #pragma unroll
        for (int s = 0; s < 4; s++) {
            float ob1 = __shfl_xor_sync(0xffffffffu, b1[s], off);
            int   oi1 = __shfl_xor_sync(0xffffffffu, i1[s], off);
            float ob2 = __shfl_xor_sync(0xffffffffu, b2[s], off);
            int   oi2 = __shfl_xor_sync(0xffffffffu, i2[s], off);
            bool takeo = (ob1 < b1[s]) || (ob1 == b1[s] && oi1 < i1[s]);
            float w1 = takeo ? ob1 : b1[s];  int wi1 = takeo ? oi1 : i1[s];
            float l1 = takeo ? b1[s] : ob1;  int li1 = takeo ? i1[s] : oi1;
            float w2 = takeo ? ob2 : b2[s];  int wi2 = takeo ? oi2 : i2[s];
            bool t2 = (l1 < w2) || (l1 == w2 && li1 < wi2);
            b1[s] = w1; i1[s] = wi1;
            b2[s] = t2 ? l1 : w2; i2[s] = t2 ? li1 : wi2;
        }
    }
    int*   sBI  = (int*)(smem + SM_BI);
    int*   sBI2 = (int*)(smem + SM_BI2);
    float* sGAP = (float*)(smem + SM_GAP);
    if ((lid & 3) == 0) {
        #pragma unroll
        for (int s = 0; s < 4; s++) {
            int row = rbase + (s >> 1) * 16 + (s & 1) * 8 + (lid >> 2);
            sBI[row]  = i1[s];
            sBI2[row] = i2[s];
            sGAP[row] = b2[s] - b1[s];
        }
    }
    __syncthreads();

    // ---------- rescue (row = tid) ----------
    int bi = sBI[tid];
    {
        const int bj = sBI2[tid];
        const float gap = sGAP[tid];
        if (gap < GAP_TAU) {
            // full exact scan over all 512 codes (rare; smem rows broadcast)
            float zv[64];
            #pragma unroll
            for (int dg = 0; dg < 16; dg++) {
                uint32_t zo = SW(tid * 128 + dg * 8);
                uint2 zh = *(uint2*)(smem + SM_AHI + zo);
                uint2 zl = *(uint2*)(smem + SM_ALO + zo);
                float2 a = u2f(zh.x), c = u2f(zl.x), d = u2f(zh.y), e = u2f(zl.y);
                zv[4 * dg + 0] = a.x + c.x; zv[4 * dg + 1] = a.y + c.y;
                zv[4 * dg + 2] = d.x + e.x; zv[4 * dg + 3] = d.y + e.y;
            }
            float bestd = 3.4e38f; int bk = 0;
            for (int k = 0; k < NUM_CODES; k++) {
                float dot = 0.f;
                #pragma unroll
                for (int dg = 0; dg < 16; dg++) {
                    uint32_t o = SW(k * 128 + dg * 8);
                    uint2 hv = *(uint2*)(smem + SM_BHI + o);
                    uint2 lv = *(uint2*)(smem + SM_BLO + o);
                    float2 p = u2f(hv.x), q = u2f(lv.x), s_ = u2f(hv.y), t_ = u2f(lv.y);
                    dot += zv[4*dg]   * (p.x + q.x) + zv[4*dg+1] * (p.y + q.y)
                         + zv[4*dg+2] * (s_.x + t_.x) + zv[4*dg+3] * (s_.y + t_.y);
                }
                float dd = esq[k] - 2.f * dot;
                if (dd < bestd) { bestd = dd; bk = k; }
            }
            bi = bk;
        } else {
            // exact fp32 recompute of the approx top-2
            float d1 = 0.f, d2 = 0.f;
            #pragma unroll
            for (int dg = 0; dg < 16; dg++) {
                uint32_t zo = SW(tid * 128 + dg * 8);
                uint2 zh = *(uint2*)(smem + SM_AHI + zo);
                uint2 zl = *(uint2*)(smem + SM_ALO + zo);
                float2 z01 = u2f(zh.x), zl01 = u2f(zl.x), z23 = u2f(zh.y), zl23 = u2f(zl.y);
                float zv0 = z01.x + zl01.x, zv1 = z01.y + zl01.y;
                float zv2 = z23.x + zl23.x, zv3 = z23.y + zl23.y;
                uint32_t o1 = SW(bi * 128 + dg * 8), o2 = SW(bj * 128 + dg * 8);
                uint2 h1 = *(uint2*)(smem + SM_BHI + o1), l1 = *(uint2*)(smem + SM_BLO + o1);
                uint2 h2v = *(uint2*)(smem + SM_BHI + o2), l2 = *(uint2*)(smem + SM_BLO + o2);
                float2 a1 = u2f(h1.x), c1 = u2f(l1.x), e1 = u2f(h1.y), f1 = u2f(l1.y);
                float2 a2 = u2f(h2v.x), c2 = u2f(l2.x), e2 = u2f(h2v.y), f2 = u2f(l2.y);
                d1 += zv0*(a1.x+c1.x) + zv1*(a1.y+c1.y) + zv2*(e1.x+f1.x) + zv3*(e1.y+f1.y);
                d2 += zv0*(a2.x+c2.x) + zv1*(a2.y+c2.y) + zv2*(e2.x+f2.x) + zv3*(e2.y+f2.y);
            }
            float x1 = esq[bi] - 2.f * d1, x2 = esq[bj] - 2.f * d2;
            if (x2 < x1 || (x2 == x1 && bj < bi)) bi = bj;
        }
    }

    // ---------- outputs ----------
    float* op = out + (size_t)b * (DIMS * HT) + r;
    float csum = 0.f;
    #pragma unroll
    for (int dg = 0; dg < 16; dg++) {
        uint32_t zo = SW(tid * 128 + dg * 8);
        uint2 zh = *(uint2*)(smem + SM_AHI + zo);
        uint2 zl = *(uint2*)(smem + SM_ALO + zo);
        float2 z01 = u2f(zh.x), zl01 = u2f(zl.x), z23 = u2f(zh.y), zl23 = u2f(zl.y);
        float zv0 = z01.x + zl01.x, zv1 = z01.y + zl01.y;
        float zv2 = z23.x + zl23.x, zv3 = z23.y + zl23.y;
        uint32_t qo = SW(bi * 128 + dg * 8);
        uint2 qh = *(uint2*)(smem + SM_BHI + qo);
        uint2 ql = *(uint2*)(smem + SM_BLO + qo);
        float2 e01 = u2f(qh.x), el01 = u2f(ql.x), e23 = u2f(qh.y), el23 = u2f(ql.y);
        float q0 = e01.x + el01.x, q1 = e01.y + el01.y, q2 = e23.x + el23.x, q3 = e23.y + el23.y;
        float d0 = q0 - zv0, d1v = q1 - zv1, d2v = q2 - zv2, d3 = q3 - zv3;
        op[(4 * dg + 0) * HT] = zv0 + d0;
        op[(4 * dg + 1) * HT] = zv1 + d1v;
        op[(4 * dg + 2) * HT] = zv2 + d2v;
        op[(4 * dg + 3) * HT] = zv3 + d3;
        csum += d0 * d0 + d1v * d1v + d2v * d2v + d3 * d3;
    }
    out[ZQ_SIZE + 1 + n] = (float)bi;
    atomicAdd(&g_counts[bi], 1);

    #pragma unroll
    for (int off = 16; off; off >>= 1)
        csum += __shfl_down_sync(0xffffffffu, csum, off);
    float* wsum = (float*)(smem + SM_WSUM);
    if (lid == 0) wsum[wid] = csum;
    __syncthreads();
    if (tid == 0) {
        float s = 0.f;
        #pragma unroll
        for (int w = 0; w < 8; w++) s += wsum[w];
        g_part[blockIdx.x] = s;
    }
}

__global__ void vq_finalize(float* __restrict__ out) {
    __shared__ float red[512];
    const int t = threadIdx.x;

    red[t] = g_part[t];
    __syncthreads();
    #pragma unroll
    for (int off = 256; off; off >>= 1) {
        if (t < off) red[t] += red[t + off];
        __syncthreads();
    }
    if (t == 0) out[ZQ_SIZE] = 0.25f * red[0] / (float)ZQ_SIZE;
    __syncthreads();

    const int c = g_counts[t];
    const float p = (float)c / (float)N_VEC;
    red[t] = -p * logf(p + 1e-12f);
    __syncthreads();
    #pragma unroll
    for (int off = 256; off; off >>= 1) {
        if (t < off) red[t] += red[t + off];
        __syncthreads();
    }
    if (t == 0) out[ZQ_SIZE + 1 + N_VEC] = expf(red[0]);
    __syncthreads();

    red[t] = (c > 0) ? 1.f : 0.f;
    __syncthreads();
    #pragma unroll
    for (int off = 256; off; off >>= 1) {
        if (t < off) red[t] += red[t + off];
        __syncthreads();
    }
    if (t == 0) out[ZQ_SIZE + 1 + N_VEC + 1] = red[0] / (float)NUM_CODES;
}

extern "C" void kernel_launch(void* const* d_in, const int* in_sizes, int n_in,
                              void* d_out, int out_size) {
    const float* z_e   = (const float*)d_in[0];
    const float* embed = (const float*)d_in[1];
    float* out = (float*)d_out;

    cudaFuncSetAttribute(vq_main, cudaFuncAttributeMaxDynamicSharedMemorySize, SMEM_TOTAL);

    vq_init<<<1, 512>>>();
    vq_main<<<512, THREADS, SMEM_TOTAL>>>(z_e, embed, out);
    vq_finalize<<<1, 512>>>(out);
}

// round 6
// speedup vs baseline: 10.5792x; 10.5792x over previous
#include <cuda_runtime.h>
#include <cuda_fp16.h>
#include <cstdint>

#define NUM_CODES 512
#define DIMS      64
#define HT        4096
#define N_VEC     131072
#define ZQ_SIZE   8388608
#define CTA_M     256
#define THREADS   256

// ---- dynamic smem layout (bytes), MMA regions 1024-aligned for SW128 ----
#define SM_AHI   0
#define SM_ALO   32768
#define SM_BHI   65536
#define SM_BLO   131072
#define SM_BI    196608
#define SM_WSUM  197632
#define SMEM_TOTAL 197696

__device__ float g_part[512];
__device__ int   g_counts[NUM_CODES];

#define SW(x) ((x) ^ ((((uint32_t)(x)) >> 3) & 0x70))

__device__ __forceinline__ uint32_t smem_u32(const void* p) {
    uint32_t a;
    asm("{ .reg .u64 t; cvta.to.shared.u64 t, %1; cvt.u32.u64 %0, t; }" : "=r"(a) : "l"(p));
    return a;
}
__device__ __forceinline__ void ldsm_x4(uint32_t& r0, uint32_t& r1, uint32_t& r2, uint32_t& r3, uint32_t a) {
    asm volatile("ldmatrix.sync.aligned.m8n8.x4.shared.b16 {%0,%1,%2,%3}, [%4];"
                 : "=r"(r0), "=r"(r1), "=r"(r2), "=r"(r3) : "r"(a));
}
__device__ __forceinline__ void mma16816(float* c, const uint32_t* a, uint32_t b0, uint32_t b1) {
    asm volatile("mma.sync.aligned.m16n8k16.row.col.f32.f16.f16.f32 "
                 "{%0,%1,%2,%3}, {%4,%5,%6,%7}, {%8,%9}, {%0,%1,%2,%3};"
                 : "+f"(c[0]), "+f"(c[1]), "+f"(c[2]), "+f"(c[3])
                 : "r"(a[0]), "r"(a[1]), "r"(a[2]), "r"(a[3]), "r"(b0), "r"(b1));
}
__device__ __forceinline__ uint32_t h2u(__half2 h) { return reinterpret_cast<uint32_t&>(h); }
__device__ __forceinline__ float2   u2f(uint32_t u) { __half2 h = reinterpret_cast<__half2&>(u); return __half22float2(h); }

__global__ void vq_init() {
    if (threadIdx.x < NUM_CODES) g_counts[threadIdx.x] = 0;
}

__global__ __launch_bounds__(THREADS, 1) void vq_main(
    const float* __restrict__ z_e, const float* __restrict__ embed,
    float* __restrict__ out)
{
    extern __shared__ char smem[];
    const uint32_t sbase = smem_u32(smem);
    const int tid = threadIdx.x, wid = tid >> 5, lid = tid & 31;

    // ---------- A fill: this thread's z vector -> f16 hi/lo, SW128 ----------
    const int n = blockIdx.x * CTA_M + tid;
    const int b = n >> 12, r = n & 4095;
    const float* zp = z_e + (size_t)b * (DIMS * HT) + r;

    #pragma unroll
    for (int i = 0; i < 8; i++) {
        uint32_t zh[4], zl[4];
        #pragma unroll
        for (int j = 0; j < 4; j++) {
            float x0 = zp[(8 * i + 2 * j) * HT];
            float x1 = zp[(8 * i + 2 * j + 1) * HT];
            __half h0 = __float2half_rn(x0), h1 = __float2half_rn(x1);
            __half l0 = __float2half_rn(x0 - __half2float(h0));
            __half l1 = __float2half_rn(x1 - __half2float(h1));
            zh[j] = h2u(__halves2half2(h0, h1));
            zl[j] = h2u(__halves2half2(l0, l1));
        }
        uint32_t off = SW(tid * 128 + i * 16);
        *(uint4*)(smem + SM_AHI + off) = make_uint4(zh[0], zh[1], zh[2], zh[3]);
        *(uint4*)(smem + SM_ALO + off) = make_uint4(zl[0], zl[1], zl[2], zl[3]);
    }

    // ---------- B fill: embedding (512x64 fp32) -> f16 hi/lo, SW128 ----------
    {
        const float4* e4 = (const float4*)embed;
        #pragma unroll 8
        for (int i = tid; i < NUM_CODES * DIMS / 4; i += THREADS) {
            float4 f = e4[i];
            int row = i >> 4, dg = i & 15;
            __half hx = __float2half_rn(f.x), hy = __float2half_rn(f.y);
            __half hz = __float2half_rn(f.z), hw = __float2half_rn(f.w);
            __half lx = __float2half_rn(f.x - __half2float(hx));
            __half ly = __float2half_rn(f.y - __half2float(hy));
            __half lz = __float2half_rn(f.z - __half2float(hz));
            __half lw = __float2half_rn(f.w - __half2float(hw));
            uint32_t off = SW(row * 128 + dg * 8);
            *(uint2*)(smem + SM_BHI + off) = make_uint2(h2u(__halves2half2(hx, hy)), h2u(__halves2half2(hz, hw)));
            *(uint2*)(smem + SM_BLO + off) = make_uint2(h2u(__halves2half2(lx, ly)), h2u(__halves2half2(lz, lw)));
        }
    }
    __syncthreads();

    // ---------- A fragments resident (warp rows rbase..rbase+31) ----------
    const int rbase = wid * 32;
    uint32_t a_hi[2][4][4], a_lo[2][4][4];
    {
        const int g = lid >> 3;
        #pragma unroll
        for (int mt = 0; mt < 2; mt++)
            #pragma unroll
            for (int kt = 0; kt < 4; kt++) {
                uint32_t row = rbase + mt * 16 + ((g & 1) << 3) + (lid & 7);
                uint32_t byte = row * 128 + kt * 32 + ((g >> 1) << 4);
                uint32_t sw = SW(byte);
                ldsm_x4(a_hi[mt][kt][0], a_hi[mt][kt][1], a_hi[mt][kt][2], a_hi[mt][kt][3],
                        sbase + SM_AHI + sw);
                ldsm_x4(a_lo[mt][kt][0], a_lo[mt][kt][1], a_lo[mt][kt][2], a_lo[mt][kt][3],
                        sbase + SM_ALO + sw);
            }
    }

    // ---------- main loop: 32 n-tile pairs, 3-pass, argmax(dot) ----------
    float m1[4] = {-3.4e38f, -3.4e38f, -3.4e38f, -3.4e38f};
    int   i1[4] = {0, 0, 0, 0};
    const uint32_t brow = ((lid >> 4) << 3) + (lid & 7);
    const uint32_t bk_off = ((lid >> 3) & 1) << 4;

    #pragma unroll 2
    for (int ntp = 0; ntp < 32; ntp++) {
        float acc[2][2][4] = {{{0.f,0.f,0.f,0.f},{0.f,0.f,0.f,0.f}},
                              {{0.f,0.f,0.f,0.f},{0.f,0.f,0.f,0.f}}};
        #pragma unroll
        for (int kt = 0; kt < 4; kt++) {
            uint32_t byte = (ntp * 16 + brow) * 128 + kt * 32 + bk_off;
            uint32_t sw = SW(byte);
            uint32_t bh0, bh1, bh2, bh3, bl0, bl1, bl2, bl3;
            ldsm_x4(bh0, bh1, bh2, bh3, sbase + SM_BHI + sw);
            ldsm_x4(bl0, bl1, bl2, bl3, sbase + SM_BLO + sw);
            #pragma unroll
            for (int mt = 0; mt < 2; mt++) {
                mma16816(acc[0][mt], a_hi[mt][kt], bh0, bh1);
                mma16816(acc[1][mt], a_hi[mt][kt], bh2, bh3);
                mma16816(acc[0][mt], a_hi[mt][kt], bl0, bl1);
                mma16816(acc[1][mt], a_hi[mt][kt], bl2, bl3);
                mma16816(acc[0][mt], a_lo[mt][kt], bh0, bh1);
                mma16816(acc[1][mt], a_lo[mt][kt], bh2, bh3);
            }
        }
        #pragma unroll
        for (int h = 0; h < 2; h++)
            #pragma unroll
            for (int mt = 0; mt < 2; mt++)
                #pragma unroll
                for (int i = 0; i < 4; i++) {
                    int s = mt * 2 + (i >> 1);
                    int k = ntp * 16 + h * 8 + 2 * (lid & 3) + (i & 1);
                    float dot = acc[h][mt][i];
                    if (dot > m1[s]) { m1[s] = dot; i1[s] = k; }
                }
    }

    // ---------- merge max(dot) across the 4 quad lanes ----------
    #pragma unroll
    for (int off = 1; off <= 2; off <<= 1) {
        #pragma unroll
        for (int s = 0; s < 4; s++) {
            float om = __shfl_xor_sync(0xffffffffu, m1[s], off);
            int   oi = __shfl_xor_sync(0xffffffffu, i1[s], off);
            bool take = (om > m1[s]) || (om == m1[s] && oi < i1[s]);
            if (take) { m1[s] = om; i1[s] = oi; }
        }
    }
    int* sBI = (int*)(smem + SM_BI);
    if ((lid & 3) == 0) {
        #pragma unroll
        for (int s = 0; s < 4; s++) {
            int row = rbase + (s >> 1) * 16 + (s & 1) * 8 + (lid >> 2);
            sBI[row] = i1[s];
        }
    }
    __syncthreads();

    // ---------- outputs (row = tid) ----------
    const int bi = sBI[tid];
    float* op = out + (size_t)b * (DIMS * HT) + r;
    float csum = 0.f;
    #pragma unroll
    for (int dg = 0; dg < 16; dg++) {
        uint32_t zo = SW(tid * 128 + dg * 8);
        uint2 zh = *(uint2*)(smem + SM_AHI + zo);
        uint2 zl = *(uint2*)(smem + SM_ALO + zo);
        float2 z01 = u2f(zh.x), zl01 = u2f(zl.x), z23 = u2f(zh.y), zl23 = u2f(zl.y);
        float zv0 = z01.x + zl01.x, zv1 = z01.y + zl01.y;
        float zv2 = z23.x + zl23.x, zv3 = z23.y + zl23.y;
        uint32_t qo = SW(bi * 128 + dg * 8);
        uint2 qh = *(uint2*)(smem + SM_BHI + qo);
        uint2 ql = *(uint2*)(smem + SM_BLO + qo);
        float2 e01 = u2f(qh.x), el01 = u2f(ql.x), e23 = u2f(qh.y), el23 = u2f(ql.y);
        float q0 = e01.x + el01.x, q1 = e01.y + el01.y, q2 = e23.x + el23.x, q3 = e23.y + el23.y;
        float d0 = q0 - zv0, d1v = q1 - zv1, d2v = q2 - zv2, d3 = q3 - zv3;
        op[(4 * dg + 0) * HT] = zv0 + d0;
        op[(4 * dg + 1) * HT] = zv1 + d1v;
        op[(4 * dg + 2) * HT] = zv2 + d2v;
        op[(4 * dg + 3) * HT] = zv3 + d3;
        csum += d0 * d0 + d1v * d1v + d2v * d2v + d3 * d3;
    }
    out[ZQ_SIZE + 1 + n] = (float)bi;
    atomicAdd(&g_counts[bi], 1);

    #pragma unroll
    for (int off = 16; off; off >>= 1)
        csum += __shfl_down_sync(0xffffffffu, csum, off);
    float* wsum = (float*)(smem + SM_WSUM);
    if (lid == 0) wsum[wid] = csum;
    __syncthreads();
    if (tid == 0) {
        float s = 0.f;
        #pragma unroll
        for (int w = 0; w < 8; w++) s += wsum[w];
        g_part[blockIdx.x] = s;
    }
}

__global__ void vq_finalize(float* __restrict__ out) {
    __shared__ float red[512];
    const int t = threadIdx.x;

    red[t] = g_part[t];
    __syncthreads();
    #pragma unroll
    for (int off = 256; off; off >>= 1) {
        if (t < off) red[t] += red[t + off];
        __syncthreads();
    }
    if (t == 0) out[ZQ_SIZE] = 0.25f * red[0] / (float)ZQ_SIZE;
    __syncthreads();

    const int c = g_counts[t];
    const float p = (float)c / (float)N_VEC;
    red[t] = -p * logf(p + 1e-12f);
    __syncthreads();
    #pragma unroll
    for (int off = 256; off; off >>= 1) {
        if (t < off) red[t] += red[t + off];
        __syncthreads();
    }
    if (t == 0) out[ZQ_SIZE + 1 + N_VEC] = expf(red[0]);
    __syncthreads();

    red[t] = (c > 0) ? 1.f : 0.f;
    __syncthreads();
    #pragma unroll
    for (int off = 256; off; off >>= 1) {
        if (t < off) red[t] += red[t + off];
        __syncthreads();
    }
    if (t == 0) out[ZQ_SIZE + 1 + N_VEC + 1] = red[0] / (float)NUM_CODES;
}

extern "C" void kernel_launch(void* const* d_in, const int* in_sizes, int n_in,
                              void* d_out, int out_size) {
    const float* z_e   = (const float*)d_in[0];
    const float* embed = (const float*)d_in[1];
    float* out = (float*)d_out;

    cudaFuncSetAttribute(vq_main, cudaFuncAttributeMaxDynamicSharedMemorySize, SMEM_TOTAL);

    vq_init<<<1, 512>>>();
    vq_main<<<512, THREADS, SMEM_TOTAL>>>(z_e, embed, out);
    vq_finalize<<<1, 512>>>(out);
}

// round 7
// speedup vs baseline: 11.0432x; 1.0439x over previous
#include <cuda_runtime.h>
#include <cuda_fp16.h>
#include <cstdint>

#define NUM_CODES 512
#define DIMS      64
#define HT        4096
#define N_VEC     131072
#define ZQ_SIZE   8388608
#define CTA_M     256
#define THREADS   256
#define GRID      148
#define NTILES    512

// ---- dynamic smem layout (bytes), MMA regions 1024-aligned for SW128 ----
#define SM_AHI   0
#define SM_ALO   32768
#define SM_BHI   65536
#define SM_BLO   131072
#define SM_BI    196608
#define SM_WSUM  197632
#define SM_RED   197696          // 512 floats for in-kernel finalize
#define SMEM_TOTAL 199744

__device__ float g_part[GRID];        // zero-init; overwritten every call
__device__ int   g_counts[NUM_CODES]; // zero-init; reset by finalize branch
__device__ int   g_done;              // zero-init; reset by finalize branch

#define SW(x) ((x) ^ ((((uint32_t)(x)) >> 3) & 0x70))

__device__ __forceinline__ uint32_t smem_u32(const void* p) {
    uint32_t a;
    asm("{ .reg .u64 t; cvta.to.shared.u64 t, %1; cvt.u32.u64 %0, t; }" : "=r"(a) : "l"(p));
    return a;
}
__device__ __forceinline__ void ldsm_x4(uint32_t& r0, uint32_t& r1, uint32_t& r2, uint32_t& r3, uint32_t a) {
    asm volatile("ldmatrix.sync.aligned.m8n8.x4.shared.b16 {%0,%1,%2,%3}, [%4];"
                 : "=r"(r0), "=r"(r1), "=r"(r2), "=r"(r3) : "r"(a));
}
__device__ __forceinline__ void mma16816(float* c, const uint32_t* a, uint32_t b0, uint32_t b1) {
    asm volatile("mma.sync.aligned.m16n8k16.row.col.f32.f16.f16.f32 "
                 "{%0,%1,%2,%3}, {%4,%5,%6,%7}, {%8,%9}, {%0,%1,%2,%3};"
                 : "+f"(c[0]), "+f"(c[1]), "+f"(c[2]), "+f"(c[3])
                 : "r"(a[0]), "r"(a[1]), "r"(a[2]), "r"(a[3]), "r"(b0), "r"(b1));
}
__device__ __forceinline__ uint32_t h2u(__half2 h) { return reinterpret_cast<uint32_t&>(h); }
__device__ __forceinline__ float2   u2f(uint32_t u) { __half2 h = reinterpret_cast<__half2&>(u); return __half22float2(h); }

__global__ __launch_bounds__(THREADS, 1) void vq_main(
    const float* __restrict__ z_e, const float* __restrict__ embed,
    float* __restrict__ out)
{
    extern __shared__ char smem[];
    const uint32_t sbase = smem_u32(smem);
    const int tid = threadIdx.x, wid = tid >> 5, lid = tid & 31;

    // ---------- B fill ONCE: embedding (512x64 fp32) -> f16 hi/lo, SW128 ----------
    {
        const float4* e4 = (const float4*)embed;
        #pragma unroll 8
        for (int i = tid; i < NUM_CODES * DIMS / 4; i += THREADS) {
            float4 f = e4[i];
            int row = i >> 4, dg = i & 15;
            __half hx = __float2half_rn(f.x), hy = __float2half_rn(f.y);
            __half hz = __float2half_rn(f.z), hw = __float2half_rn(f.w);
            __half lx = __float2half_rn(f.x - __half2float(hx));
            __half ly = __float2half_rn(f.y - __half2float(hy));
            __half lz = __float2half_rn(f.z - __half2float(hz));
            __half lw = __float2half_rn(f.w - __half2float(hw));
            uint32_t off = SW(row * 128 + dg * 8);
            *(uint2*)(smem + SM_BHI + off) = make_uint2(h2u(__halves2half2(hx, hy)), h2u(__halves2half2(hz, hw)));
            *(uint2*)(smem + SM_BLO + off) = make_uint2(h2u(__halves2half2(lx, ly)), h2u(__halves2half2(lz, lw)));
        }
    }

    const int rbase = wid * 32;
    const uint32_t brow = ((lid >> 4) << 3) + (lid & 7);
    const uint32_t bk_off = ((lid >> 3) & 1) << 4;
    int* sBI = (int*)(smem + SM_BI);
    float csum_total = 0.f;

    // ================= persistent tile loop =================
    for (int tile = blockIdx.x; tile < NTILES; tile += GRID) {
        // ---------- A fill: this thread's z vector -> f16 hi/lo, SW128 ----------
        const int n = tile * CTA_M + tid;
        const int b = n >> 12, r = n & 4095;
        const float* zp = z_e + (size_t)b * (DIMS * HT) + r;

        #pragma unroll
        for (int i = 0; i < 8; i++) {
            uint32_t zh[4], zl[4];
            #pragma unroll
            for (int j = 0; j < 4; j++) {
                float x0 = zp[(8 * i + 2 * j) * HT];
                float x1 = zp[(8 * i + 2 * j + 1) * HT];
                __half h0 = __float2half_rn(x0), h1 = __float2half_rn(x1);
                __half l0 = __float2half_rn(x0 - __half2float(h0));
                __half l1 = __float2half_rn(x1 - __half2float(h1));
                zh[j] = h2u(__halves2half2(h0, h1));
                zl[j] = h2u(__halves2half2(l0, l1));
            }
            uint32_t off = SW(tid * 128 + i * 16);
            *(uint4*)(smem + SM_AHI + off) = make_uint4(zh[0], zh[1], zh[2], zh[3]);
            *(uint4*)(smem + SM_ALO + off) = make_uint4(zl[0], zl[1], zl[2], zl[3]);
        }
        __syncthreads();   // A (and on iter 0, B) ready

        // ---------- A fragments ----------
        uint32_t a_hi[2][4][4], a_lo[2][4][4];
        {
            const int g = lid >> 3;
            #pragma unroll
            for (int mt = 0; mt < 2; mt++)
                #pragma unroll
                for (int kt = 0; kt < 4; kt++) {
                    uint32_t row = rbase + mt * 16 + ((g & 1) << 3) + (lid & 7);
                    uint32_t byte = row * 128 + kt * 32 + ((g >> 1) << 4);
                    uint32_t sw = SW(byte);
                    ldsm_x4(a_hi[mt][kt][0], a_hi[mt][kt][1], a_hi[mt][kt][2], a_hi[mt][kt][3],
                            sbase + SM_AHI + sw);
                    ldsm_x4(a_lo[mt][kt][0], a_lo[mt][kt][1], a_lo[mt][kt][2], a_lo[mt][kt][3],
                            sbase + SM_ALO + sw);
                }
        }

        // ---------- main loop: 32 n-tile pairs, 3-pass, argmax(dot) ----------
        float m1[4] = {-3.4e38f, -3.4e38f, -3.4e38f, -3.4e38f};
        int   i1[4] = {0, 0, 0, 0};

        #pragma unroll 2
        for (int ntp = 0; ntp < 32; ntp++) {
            float acc[2][2][4] = {{{0.f,0.f,0.f,0.f},{0.f,0.f,0.f,0.f}},
                                  {{0.f,0.f,0.f,0.f},{0.f,0.f,0.f,0.f}}};
            #pragma unroll
            for (int kt = 0; kt < 4; kt++) {
                uint32_t byte = (ntp * 16 + brow) * 128 + kt * 32 + bk_off;
                uint32_t sw = SW(byte);
                uint32_t bh0, bh1, bh2, bh3, bl0, bl1, bl2, bl3;
                ldsm_x4(bh0, bh1, bh2, bh3, sbase + SM_BHI + sw);
                ldsm_x4(bl0, bl1, bl2, bl3, sbase + SM_BLO + sw);
                #pragma unroll
                for (int mt = 0; mt < 2; mt++) {
                    mma16816(acc[0][mt], a_hi[mt][kt], bh0, bh1);
                    mma16816(acc[1][mt], a_hi[mt][kt], bh2, bh3);
                    mma16816(acc[0][mt], a_hi[mt][kt], bl0, bl1);
                    mma16816(acc[1][mt], a_hi[mt][kt], bl2, bl3);
                    mma16816(acc[0][mt], a_lo[mt][kt], bh0, bh1);
                    mma16816(acc[1][mt], a_lo[mt][kt], bh2, bh3);
                }
            }
            #pragma unroll
            for (int h = 0; h < 2; h++)
                #pragma unroll
                for (int mt = 0; mt < 2; mt++)
                    #pragma unroll
                    for (int i = 0; i < 4; i++) {
                        int s = mt * 2 + (i >> 1);
                        int k = ntp * 16 + h * 8 + 2 * (lid & 3) + (i & 1);
                        float dot = acc[h][mt][i];
                        if (dot > m1[s]) { m1[s] = dot; i1[s] = k; }
                    }
        }

        // ---------- merge max(dot) across the 4 quad lanes ----------
        #pragma unroll
        for (int off = 1; off <= 2; off <<= 1) {
            #pragma unroll
            for (int s = 0; s < 4; s++) {
                float om = __shfl_xor_sync(0xffffffffu, m1[s], off);
                int   oi = __shfl_xor_sync(0xffffffffu, i1[s], off);
                bool take = (om > m1[s]) || (om == m1[s] && oi < i1[s]);
                if (take) { m1[s] = om; i1[s] = oi; }
            }
        }
        if ((lid & 3) == 0) {
            #pragma unroll
            for (int s = 0; s < 4; s++) {
                int row = rbase + (s >> 1) * 16 + (s & 1) * 8 + (lid >> 2);
                sBI[row] = i1[s];
            }
        }
        __syncthreads();

        // ---------- outputs (row = tid) ----------
        const int bi = sBI[tid];
        float* op = out + (size_t)b * (DIMS * HT) + r;
        float csum = 0.f;
        #pragma unroll
        for (int dg = 0; dg < 16; dg++) {
            uint32_t zo = SW(tid * 128 + dg * 8);
            uint2 zh = *(uint2*)(smem + SM_AHI + zo);
            uint2 zl = *(uint2*)(smem + SM_ALO + zo);
            float2 z01 = u2f(zh.x), zl01 = u2f(zl.x), z23 = u2f(zh.y), zl23 = u2f(zl.y);
            float zv0 = z01.x + zl01.x, zv1 = z01.y + zl01.y;
            float zv2 = z23.x + zl23.x, zv3 = z23.y + zl23.y;
            uint32_t qo = SW(bi * 128 + dg * 8);
            uint2 qh = *(uint2*)(smem + SM_BHI + qo);
            uint2 ql = *(uint2*)(smem + SM_BLO + qo);
            float2 e01 = u2f(qh.x), el01 = u2f(ql.x), e23 = u2f(qh.y), el23 = u2f(ql.y);
            float q0 = e01.x + el01.x, q1 = e01.y + el01.y, q2 = e23.x + el23.x, q3 = e23.y + el23.y;
            float d0 = q0 - zv0, d1v = q1 - zv1, d2v = q2 - zv2, d3 = q3 - zv3;
            op[(4 * dg + 0) * HT] = zv0 + d0;
            op[(4 * dg + 1) * HT] = zv1 + d1v;
            op[(4 * dg + 2) * HT] = zv2 + d2v;
            op[(4 * dg + 3) * HT] = zv3 + d3;
            csum += d0 * d0 + d1v * d1v + d2v * d2v + d3 * d3;
        }
        out[ZQ_SIZE + 1 + n] = (float)bi;
        atomicAdd(&g_counts[bi], 1);
        csum_total += csum;

        __syncthreads();   // protect A smem / sBI before next tile
    }

    // ---------- per-CTA commitment partial ----------
    #pragma unroll
    for (int off = 16; off; off >>= 1)
        csum_total += __shfl_down_sync(0xffffffffu, csum_total, off);
    float* wsum = (float*)(smem + SM_WSUM);
    if (lid == 0) wsum[wid] = csum_total;
    __syncthreads();
    if (tid == 0) {
        float s = 0.f;
        #pragma unroll
        for (int w = 0; w < 8; w++) s += wsum[w];
        g_part[blockIdx.x] = s;
    }

    // ---------- last-CTA in-kernel finalize ----------
    __threadfence();
    __shared__ int s_last;
    if (tid == 0) s_last = (atomicAdd(&g_done, 1) == GRID - 1);
    __syncthreads();
    if (s_last) {
        __threadfence();
        float* red = (float*)(smem + SM_RED);

        // commitment
        red[tid] = (tid < GRID) ? g_part[tid] : 0.f;
        __syncthreads();
        #pragma unroll
        for (int off = 128; off; off >>= 1) {
            if (tid < off) red[tid] += red[tid + off];
            __syncthreads();
        }
        if (tid == 0) out[ZQ_SIZE] = 0.25f * red[0] / (float)ZQ_SIZE;
        __syncthreads();

        // entropy -> perplexity  (512 codes, 2 per thread)
        const int c0 = g_counts[tid], c1 = g_counts[tid + 256];
        {
            float p0 = (float)c0 / (float)N_VEC, p1 = (float)c1 / (float)N_VEC;
            red[tid] = -p0 * logf(p0 + 1e-12f) - p1 * logf(p1 + 1e-12f);
        }
        __syncthreads();
        #pragma unroll
        for (int off = 128; off; off >>= 1) {
            if (tid < off) red[tid] += red[tid + off];
            __syncthreads();
        }
        if (tid == 0) out[ZQ_SIZE + 1 + N_VEC] = expf(red[0]);
        __syncthreads();

        // usage
        red[tid] = ((c0 > 0) ? 1.f : 0.f) + ((c1 > 0) ? 1.f : 0.f);
        __syncthreads();
        #pragma unroll
        for (int off = 128; off; off >>= 1) {
            if (tid < off) red[tid] += red[tid + off];
            __syncthreads();
        }
        if (tid == 0) out[ZQ_SIZE + 1 + N_VEC + 1] = red[0] / (float)NUM_CODES;

        // reset state for next graph replay
        g_counts[tid] = 0;
        g_counts[tid + 256] = 0;
        if (tid == 0) g_done = 0;
    }
}

extern "C" void kernel_launch(void* const* d_in, const int* in_sizes, int n_in,
                              void* d_out, int out_size) {
    const float* z_e   = (const float*)d_in[0];
    const float* embed = (const float*)d_in[1];
    float* out = (float*)d_out;

    cudaFuncSetAttribute(vq_main, cudaFuncAttributeMaxDynamicSharedMemorySize, SMEM_TOTAL);
    vq_main<<<GRID, THREADS, SMEM_TOTAL>>>(z_e, embed, out);
}